// round 9
// baseline (speedup 1.0000x reference)
#include <cuda_runtime.h>
#include <cuda_fp16.h>
#include <cstddef>

#define N_USER  100000
#define N_ITEM  50000
#define N_NODES 150000
#define EMB     64
#define N_EDGES 4000000
#define BATCH   4096
#define PW_INV_LAYERS 0.25f   // 1/(N_LAYERS+1)
#define TB 256
#define NBLK ((N_NODES + TB - 1) / TB)   // 586 scan blocks

// ---- device-global scratch (allocation-free) ----
__device__ __half g_c0[(size_t)N_NODES * EMB];
__device__ __half g_c1[(size_t)N_NODES * EMB];
__device__ __half g_c2[(size_t)N_NODES * EMB];
__device__ int    g_cnt   [N_NODES];        // zero-init; re-zeroed by scan
__device__ int    g_fill  [N_NODES];
__device__ int    g_rowptr[N_NODES + 1];
__device__ int2   g_perm  [N_EDGES];        // (col, val-as-fp32-bits) 32 MB
// decoupled-lookback state (reset by k_init_hist every replay)
__device__ int          g_aggr[NBLK];
__device__ int          g_pref[NBLK];
__device__ volatile int g_flag[NBLK];       // 0=invalid 1=aggregate 2=prefix

// ---------------------------------------------------------------------------
// init + hist fused (vectorized, 4 edges/thread) + lookback-flag reset
// ---------------------------------------------------------------------------
__global__ void k_init_hist(const float* __restrict__ ue,
                            const float* __restrict__ ie,
                            const int*   __restrict__ rows) {
    int i = blockIdx.x * blockDim.x + threadIdx.x;
    if (i < NBLK) g_flag[i] = 0;
    if (i < N_EDGES / 4) {
        int4 r4 = __ldg((const int4*)rows + i);
        atomicAdd(&g_cnt[r4.x], 1);
        atomicAdd(&g_cnt[r4.y], 1);
        atomicAdd(&g_cnt[r4.z], 1);
        atomicAdd(&g_cnt[r4.w], 1);
    }
    if (i < N_NODES * 32) {
        const float2* u2 = (const float2*)ue;
        const float2* i2 = (const float2*)ie;
        float2 v = (i < N_USER * 32) ? u2[i] : i2[i - N_USER * 32];
        ((half2*)g_c0)[i] = __floats2half2_rn(v.x, v.y);
    }
}

// ---------------------------------------------------------------------------
// single-launch decoupled-lookback exclusive scan of g_cnt -> g_rowptr/g_fill
// (also re-zeroes g_cnt for the next replay). 586 blocks, all co-resident.
// ---------------------------------------------------------------------------
__global__ void __launch_bounds__(TB) k_scan_lookback() {
    __shared__ int sh_warp[TB / 32];
    __shared__ int sh_base;
    int bid  = blockIdx.x;
    int tid  = threadIdx.x;
    int lane = tid & 31;
    int wid  = tid >> 5;
    int i = bid * TB + tid;

    int c = (i < N_NODES) ? g_cnt[i] : 0;

    // warp inclusive scan
    int incl = c;
    #pragma unroll
    for (int off = 1; off < 32; off <<= 1) {
        int t = __shfl_up_sync(0xffffffffu, incl, off);
        if (lane >= off) incl += t;
    }
    if (lane == 31) sh_warp[wid] = incl;
    __syncthreads();
    if (wid == 0) {
        int w = (lane < TB / 32) ? sh_warp[lane] : 0;
        #pragma unroll
        for (int off = 1; off < TB / 32; off <<= 1) {
            int t = __shfl_up_sync(0xffffffffu, w, off);
            if (lane >= off) w += t;
        }
        if (lane < TB / 32) sh_warp[lane] = w;   // inclusive warp offsets
    }
    __syncthreads();
    int block_incl = incl + (wid > 0 ? sh_warp[wid - 1] : 0);
    int block_total = sh_warp[TB / 32 - 1];

    // thread 0: publish aggregate, look back, publish prefix
    if (tid == 0) {
        g_aggr[bid] = block_total;
        __threadfence();
        g_flag[bid] = 1;
        int run = 0;
        int j = bid - 1;
        while (j >= 0) {
            int f = g_flag[j];
            if (f == 2) { run += g_pref[j]; break; }
            if (f == 1) { run += g_aggr[j]; j--; }
            // f == 0: spin
        }
        g_pref[bid] = run + block_total;
        __threadfence();
        g_flag[bid] = 2;
        sh_base = run;
    }
    __syncthreads();
    int excl = sh_base + block_incl - c;
    if (i < N_NODES) { g_rowptr[i] = excl; g_fill[i] = excl; g_cnt[i] = 0; }
    if (i == 0) g_rowptr[N_NODES] = N_EDGES;
}

// ---------------------------------------------------------------------------
// CSR build: permute (col, val) into row-grouped order (4 edges/thread)
// ---------------------------------------------------------------------------
__global__ void k_permute(const int*   __restrict__ rows,
                          const int*   __restrict__ cols,
                          const float* __restrict__ vals) {
    int t = blockIdx.x * blockDim.x + threadIdx.x;
    if (t >= N_EDGES / 4) return;
    int4   r4 = __ldg((const int4*)rows + t);
    int4   c4 = __ldg((const int4*)cols + t);
    float4 v4 = __ldg((const float4*)vals + t);
    int i0 = atomicAdd(&g_fill[r4.x], 1);
    g_perm[i0] = make_int2(c4.x, __float_as_int(v4.x));
    int i1 = atomicAdd(&g_fill[r4.y], 1);
    g_perm[i1] = make_int2(c4.y, __float_as_int(v4.y));
    int i2 = atomicAdd(&g_fill[r4.z], 1);
    g_perm[i2] = make_int2(c4.z, __float_as_int(v4.z));
    int i3 = atomicAdd(&g_fill[r4.w], 1);
    g_perm[i3] = make_int2(c4.w, __float_as_int(v4.w));
}

// ---------------------------------------------------------------------------
// Warp-level row accumulation core (smem-staged, fixed-32 unrolled inner loop;
// inactive entries (0,0) gather L1-hot row 0 with weight 0 — harmless).
// ---------------------------------------------------------------------------
__device__ __forceinline__ float2 row_accumulate(const __half* __restrict__ src,
                                                 int beg, int end, int lane,
                                                 int2* __restrict__ slab) {
    float2 s = make_float2(0.f, 0.f);
    for (int base = beg; base < end; base += 32) {
        int n = end - base;
        int2 ev = make_int2(0, 0);
        if (lane < n) ev = __ldg(&g_perm[base + lane]);
        __syncwarp();
        slab[lane] = ev;
        __syncwarp();
        #pragma unroll
        for (int j = 0; j < 32; j++) {
            int2  e = slab[j];
            float v = __int_as_float(e.y);
            float2 x = __half22float2(
                *(const half2*)(src + (size_t)e.x * EMB + lane * 2));
            s.x = fmaf(v, x.x, s.x);
            s.y = fmaf(v, x.y, s.y);
        }
    }
    return s;
}

// ---------------------------------------------------------------------------
// full layer: one warp per row, atomic-free pull (fp16 in, fp32 accum)
// ---------------------------------------------------------------------------
template <int APPLY_POP>
__global__ void __launch_bounds__(TB)
k_layer(const __half* __restrict__ src,
        __half*       __restrict__ dst,
        const float*  __restrict__ upi,
        const float*  __restrict__ ipi) {
    __shared__ int2 sh[TB / 32][32];
    int gid  = blockIdx.x * blockDim.x + threadIdx.x;
    int row  = gid >> 5;
    int lane = gid & 31;
    int wid  = threadIdx.x >> 5;
    if (row >= N_NODES) return;

    int beg = __ldg(&g_rowptr[row]);
    int end = __ldg(&g_rowptr[row + 1]);

    float2 s = row_accumulate(src, beg, end, lane, sh[wid]);

    if (APPLY_POP) {
        float sc = (row < N_USER) ? __ldg(upi + row) : __ldg(ipi + (row - N_USER));
        s.x *= sc; s.y *= sc;
    }

    ((half2*)dst)[(size_t)row * 32 + lane] = __floats2half2_rn(s.x, s.y);
}

// ---------------------------------------------------------------------------
// fused layer-3 + gather: one warp per batch slot; c3 computed in registers
// for the ~12K sampled rows only.
//   out[sec]   = 0.25*(emb + pw*(c1+c2+c3))   sec 0..2
//   out[3+sec] = emb
// ---------------------------------------------------------------------------
__global__ void __launch_bounds__(TB)
k_l3_gather(const float* __restrict__ ue,
            const float* __restrict__ ie,
            const float* __restrict__ pwp,
            const int*   __restrict__ users,
            const int*   __restrict__ pos,
            const int*   __restrict__ neg,
            float* __restrict__ out) {
    __shared__ int2 sh[TB / 32][32];
    int gid  = blockIdx.x * blockDim.x + threadIdx.x;
    int w    = gid >> 5;
    int lane = gid & 31;
    int wid  = threadIdx.x >> 5;
    if (w >= 3 * BATCH) return;
    int sec = w / BATCH;
    int b   = w - sec * BATCH;

    int node; const float* emb;
    if (sec == 0)      { int u = __ldg(users + b); node = u;          emb = ue + (size_t)u * EMB; }
    else if (sec == 1) { int p = __ldg(pos + b);   node = N_USER + p; emb = ie + (size_t)p * EMB; }
    else               { int p = __ldg(neg + b);   node = N_USER + p; emb = ie + (size_t)p * EMB; }

    int beg = __ldg(&g_rowptr[node]);
    int end = __ldg(&g_rowptr[node + 1]);
    float2 s = row_accumulate(g_c2, beg, end, lane, sh[wid]);

    float pw = __ldg(pwp);
    size_t off = (size_t)node * 32 + lane;
    float2 e  = ((const float2*)emb)[lane];
    float2 c1 = __half22float2(((const half2*)g_c1)[off]);
    float2 c2 = __half22float2(((const half2*)g_c2)[off]);

    float2 o;
    o.x = PW_INV_LAYERS * (e.x + pw * (c1.x + c2.x + s.x));
    o.y = PW_INV_LAYERS * (e.y + pw * (c1.y + c2.y + s.y));

    size_t slot = (size_t)b * 32 + lane;
    ((float2*)out)[(size_t)sec * BATCH * 32 + slot]       = o;
    ((float2*)out)[(size_t)(3 + sec) * BATCH * 32 + slot] = e;
}

// ---------------------------------------------------------------------------
// kernel_launch
// Inputs: user_emb, item_emb, edge_rows, edge_cols, edge_vals,
//         user_pop_inv, item_pop_inv, popularity_weight, users, pos, neg
// ---------------------------------------------------------------------------
extern "C" void kernel_launch(void* const* d_in, const int* in_sizes, int n_in,
                              void* d_out, int out_size) {
    const float* ue    = (const float*)d_in[0];
    const float* ie    = (const float*)d_in[1];
    const int*   erow  = (const int*)  d_in[2];
    const int*   ecol  = (const int*)  d_in[3];
    const float* eval_ = (const float*)d_in[4];
    const float* upi   = (const float*)d_in[5];
    const float* ipi   = (const float*)d_in[6];
    const float* pwp   = (const float*)d_in[7];
    const int*   users = (const int*)  d_in[8];
    const int*   pos   = (const int*)  d_in[9];
    const int*   neg   = (const int*)  d_in[10];
    float* out = (float*)d_out;

    __half *c0, *c1, *c2;
    cudaGetSymbolAddress((void**)&c0, g_c0);
    cudaGetSymbolAddress((void**)&c1, g_c1);
    cudaGetSymbolAddress((void**)&c2, g_c2);

    const int inith_grid    = (N_NODES * 32 + TB - 1) / TB;   // covers 1M edge-quads too
    const int perm_grid     = (N_EDGES / 4 + TB - 1) / TB;
    const int row_warp_grid = (N_NODES * 32 + TB - 1) / TB;   // 1 warp/row
    const int l3g_grid      = (3 * BATCH * 32 + TB - 1) / TB;

    // init + CSR build (every replay; deterministic)
    k_init_hist<<<inith_grid, TB>>>(ue, ie, erow);
    k_scan_lookback<<<NBLK, TB>>>();
    k_permute<<<perm_grid, TB>>>(erow, ecol, eval_);

    // layers 1 and 2 over all nodes (atomic-free pull, fp16 features)
    k_layer<1><<<row_warp_grid, TB>>>(c0, c1, upi, ipi);
    k_layer<0><<<row_warp_grid, TB>>>(c1, c2, upi, ipi);

    // layer 3 restricted to sampled rows, fused with output gather
    k_l3_gather<<<l3g_grid, TB>>>(ue, ie, pwp, users, pos, neg, out);

    (void)in_sizes; (void)n_in; (void)out_size;
}

// round 10
// speedup vs baseline: 1.1681x; 1.1681x over previous
#include <cuda_runtime.h>
#include <cuda_fp16.h>
#include <cstddef>

#define N_USER  100000
#define N_ITEM  50000
#define N_NODES 150000
#define EMB     64
#define N_EDGES 4000000
#define BATCH   4096
#define PW_INV_LAYERS 0.25f   // 1/(N_LAYERS+1)
#define TB 256
#define NBLK ((N_NODES + TB - 1) / TB)   // 586 scan blocks

// ---- device-global scratch (allocation-free) ----
__device__ __half g_c0[(size_t)N_NODES * EMB];
__device__ __half g_c1[(size_t)N_NODES * EMB];
__device__ __half g_c2[(size_t)N_NODES * EMB];
__device__ int    g_cnt   [N_NODES];        // zero-init; re-zeroed by k_scan3
__device__ int    g_fill  [N_NODES];
__device__ int    g_rowptr[N_NODES + 1];
__device__ int    g_bsum  [1024];
__device__ int2   g_perm  [N_EDGES];        // (col, val as duplicated half2) 32 MB

// ---------------------------------------------------------------------------
// init + hist fused (scalar — R8 version; R9 vectorization regressed)
// ---------------------------------------------------------------------------
__global__ void k_init_hist(const float* __restrict__ ue,
                            const float* __restrict__ ie,
                            const int*   __restrict__ rows) {
    int i = blockIdx.x * blockDim.x + threadIdx.x;
    if (i < N_EDGES)
        atomicAdd(&g_cnt[__ldg(rows + i)], 1);
    if (i < N_NODES * 32) {
        const float2* u2 = (const float2*)ue;
        const float2* i2 = (const float2*)ie;
        float2 v = (i < N_USER * 32) ? u2[i] : i2[i - N_USER * 32];
        ((half2*)g_c0)[i] = __floats2half2_rn(v.x, v.y);
    }
}

// ---------------------------------------------------------------------------
// CSR scan a: per-block sums   (R8 3-launch scan restored)
// ---------------------------------------------------------------------------
__global__ void k_scan1() {
    __shared__ int sh[TB];
    int i = blockIdx.x * TB + threadIdx.x;
    int c = (i < N_NODES) ? g_cnt[i] : 0;
    sh[threadIdx.x] = c; __syncthreads();
    for (int off = TB / 2; off > 0; off >>= 1) {
        if (threadIdx.x < off) sh[threadIdx.x] += sh[threadIdx.x + off];
        __syncthreads();
    }
    if (threadIdx.x == 0) g_bsum[blockIdx.x] = sh[0];
}

// ---------------------------------------------------------------------------
// CSR scan b: exclusive scan of block sums (single block)
// ---------------------------------------------------------------------------
__global__ void k_scan2() {
    __shared__ int sh[1024];
    int t = threadIdx.x;
    int v = (t < NBLK) ? g_bsum[t] : 0;
    sh[t] = v; __syncthreads();
    for (int off = 1; off < 1024; off <<= 1) {
        int add = (t >= off) ? sh[t - off] : 0;
        __syncthreads();
        sh[t] += add;
        __syncthreads();
    }
    if (t < NBLK) g_bsum[t] = sh[t] - v;   // exclusive
}

// ---------------------------------------------------------------------------
// CSR scan c: row_ptr + fill cursors; re-zeroes g_cnt for next replay
// ---------------------------------------------------------------------------
__global__ void k_scan3() {
    __shared__ int sh[TB];
    int i = blockIdx.x * TB + threadIdx.x;
    int c = (i < N_NODES) ? g_cnt[i] : 0;
    sh[threadIdx.x] = c; __syncthreads();
    for (int off = 1; off < TB; off <<= 1) {
        int add = (threadIdx.x >= off) ? sh[threadIdx.x - off] : 0;
        __syncthreads();
        sh[threadIdx.x] += add;
        __syncthreads();
    }
    int excl = sh[threadIdx.x] - c + g_bsum[blockIdx.x];
    if (i < N_NODES) { g_rowptr[i] = excl; g_fill[i] = excl; g_cnt[i] = 0; }
    if (i == 0) g_rowptr[N_NODES] = N_EDGES;
}

// ---------------------------------------------------------------------------
// CSR build: permute into row-grouped order; val stored as duplicated half2
// (scalar 1-edge/thread — R8 version restored)
// ---------------------------------------------------------------------------
__global__ void k_permute(const int*   __restrict__ rows,
                          const int*   __restrict__ cols,
                          const float* __restrict__ vals) {
    int e = blockIdx.x * blockDim.x + threadIdx.x;
    if (e >= N_EDGES) return;
    int r = __ldg(rows + e);
    int idx = atomicAdd(&g_fill[r], 1);
    unsigned h = (unsigned)__half_as_ushort(__float2half_rn(__ldg(vals + e)));
    g_perm[idx] = make_int2(__ldg(cols + e), (int)(h * 0x10001u));
}

// ---------------------------------------------------------------------------
// Warp-level row accumulation core, HFMA2 edition:
// - stage 32 (col, half2-val) entries in the warp's smem slab
// - fixed 16-trip unrolled loop, 2 edges per LDS.128
// - half2 accumulator within a chunk (<=32 products), flushed to fp32/chunk
// - inactive entries (0,0): gather L1-hot row 0 with half2 weight 0
// ---------------------------------------------------------------------------
__device__ __forceinline__ float2 row_accumulate(const __half* __restrict__ src,
                                                 int beg, int end, int lane,
                                                 int2* __restrict__ slab) {
    float2 s = make_float2(0.f, 0.f);
    for (int base = beg; base < end; base += 32) {
        int n = end - base;
        int2 ev = make_int2(0, 0);
        if (lane < n) ev = __ldg(&g_perm[base + lane]);
        __syncwarp();
        slab[lane] = ev;
        __syncwarp();
        half2 a0 = __float2half2_rn(0.f);
        const int4* slab4 = (const int4*)slab;
        #pragma unroll
        for (int j = 0; j < 16; j++) {
            int4 e2 = slab4[j];
            half2 v0 = *(half2*)&e2.y;
            half2 v1 = *(half2*)&e2.w;
            half2 x0 = *(const half2*)(src + (size_t)e2.x * EMB + lane * 2);
            half2 x1 = *(const half2*)(src + (size_t)e2.z * EMB + lane * 2);
            a0 = __hfma2(v0, x0, a0);
            a0 = __hfma2(v1, x1, a0);
        }
        float2 a = __half22float2(a0);
        s.x += a.x; s.y += a.y;
        __syncwarp();
    }
    return s;
}

// ---------------------------------------------------------------------------
// full layer: one warp per row, atomic-free pull
// ---------------------------------------------------------------------------
template <int APPLY_POP>
__global__ void __launch_bounds__(TB)
k_layer(const __half* __restrict__ src,
        __half*       __restrict__ dst,
        const float*  __restrict__ upi,
        const float*  __restrict__ ipi) {
    __shared__ __align__(16) int2 sh[TB / 32][32];
    int gid  = blockIdx.x * blockDim.x + threadIdx.x;
    int row  = gid >> 5;
    int lane = gid & 31;
    int wid  = threadIdx.x >> 5;
    if (row >= N_NODES) return;

    int beg = __ldg(&g_rowptr[row]);
    int end = __ldg(&g_rowptr[row + 1]);

    float2 s = row_accumulate(src, beg, end, lane, sh[wid]);

    if (APPLY_POP) {
        float sc = (row < N_USER) ? __ldg(upi + row) : __ldg(ipi + (row - N_USER));
        s.x *= sc; s.y *= sc;
    }

    ((half2*)dst)[(size_t)row * 32 + lane] = __floats2half2_rn(s.x, s.y);
}

// ---------------------------------------------------------------------------
// fused layer-3 + gather: one warp per batch slot; c3 computed in registers
// for the ~12K sampled rows only.
//   out[sec]   = 0.25*(emb + pw*(c1+c2+c3))   sec 0..2
//   out[3+sec] = emb
// ---------------------------------------------------------------------------
__global__ void __launch_bounds__(TB)
k_l3_gather(const float* __restrict__ ue,
            const float* __restrict__ ie,
            const float* __restrict__ pwp,
            const int*   __restrict__ users,
            const int*   __restrict__ pos,
            const int*   __restrict__ neg,
            float* __restrict__ out) {
    __shared__ __align__(16) int2 sh[TB / 32][32];
    int gid  = blockIdx.x * blockDim.x + threadIdx.x;
    int w    = gid >> 5;
    int lane = gid & 31;
    int wid  = threadIdx.x >> 5;
    if (w >= 3 * BATCH) return;
    int sec = w / BATCH;
    int b   = w - sec * BATCH;

    int node; const float* emb;
    if (sec == 0)      { int u = __ldg(users + b); node = u;          emb = ue + (size_t)u * EMB; }
    else if (sec == 1) { int p = __ldg(pos + b);   node = N_USER + p; emb = ie + (size_t)p * EMB; }
    else               { int p = __ldg(neg + b);   node = N_USER + p; emb = ie + (size_t)p * EMB; }

    int beg = __ldg(&g_rowptr[node]);
    int end = __ldg(&g_rowptr[node + 1]);
    float2 s = row_accumulate(g_c2, beg, end, lane, sh[wid]);

    float pw = __ldg(pwp);
    size_t off = (size_t)node * 32 + lane;
    float2 e  = ((const float2*)emb)[lane];
    float2 c1 = __half22float2(((const half2*)g_c1)[off]);
    float2 c2 = __half22float2(((const half2*)g_c2)[off]);

    float2 o;
    o.x = PW_INV_LAYERS * (e.x + pw * (c1.x + c2.x + s.x));
    o.y = PW_INV_LAYERS * (e.y + pw * (c1.y + c2.y + s.y));

    size_t slot = (size_t)b * 32 + lane;
    ((float2*)out)[(size_t)sec * BATCH * 32 + slot]       = o;
    ((float2*)out)[(size_t)(3 + sec) * BATCH * 32 + slot] = e;
}

// ---------------------------------------------------------------------------
// kernel_launch
// Inputs: user_emb, item_emb, edge_rows, edge_cols, edge_vals,
//         user_pop_inv, item_pop_inv, popularity_weight, users, pos, neg
// ---------------------------------------------------------------------------
extern "C" void kernel_launch(void* const* d_in, const int* in_sizes, int n_in,
                              void* d_out, int out_size) {
    const float* ue    = (const float*)d_in[0];
    const float* ie    = (const float*)d_in[1];
    const int*   erow  = (const int*)  d_in[2];
    const int*   ecol  = (const int*)  d_in[3];
    const float* eval_ = (const float*)d_in[4];
    const float* upi   = (const float*)d_in[5];
    const float* ipi   = (const float*)d_in[6];
    const float* pwp   = (const float*)d_in[7];
    const int*   users = (const int*)  d_in[8];
    const int*   pos   = (const int*)  d_in[9];
    const int*   neg   = (const int*)  d_in[10];
    float* out = (float*)d_out;

    __half *c0, *c1, *c2;
    cudaGetSymbolAddress((void**)&c0, g_c0);
    cudaGetSymbolAddress((void**)&c1, g_c1);
    cudaGetSymbolAddress((void**)&c2, g_c2);

    const int inith_grid    = (N_NODES * 32 + TB - 1) / TB;
    const int edge_grid     = (N_EDGES + TB - 1) / TB;
    const int row_warp_grid = (N_NODES * 32 + TB - 1) / TB;   // 1 warp/row
    const int l3g_grid      = (3 * BATCH * 32 + TB - 1) / TB;

    // init + CSR build (every replay; deterministic)
    k_init_hist<<<inith_grid, TB>>>(ue, ie, erow);
    k_scan1<<<NBLK, TB>>>();
    k_scan2<<<1, 1024>>>();
    k_scan3<<<NBLK, TB>>>();
    k_permute<<<edge_grid, TB>>>(erow, ecol, eval_);

    // layers 1 and 2 over all nodes (atomic-free pull, HFMA2 inner loop)
    k_layer<1><<<row_warp_grid, TB>>>(c0, c1, upi, ipi);
    k_layer<0><<<row_warp_grid, TB>>>(c1, c2, upi, ipi);

    // layer 3 restricted to sampled rows, fused with output gather
    k_l3_gather<<<l3g_grid, TB>>>(ue, ie, pwp, users, pos, neg, out);

    (void)in_sizes; (void)n_in; (void)out_size;
}